// round 11
// baseline (speedup 1.0000x reference)
#include <cuda_runtime.h>
#include <math.h>

#define SEQ      512
#define BATCH    2
#define DMODEL   1024
#define DINNER   2048
#define DSTATE   16
#define DTRANK   64
#define NLAYERS  4
#define MROWS    (BATCH * SEQ)          /* 1024 */
#define XZW      (2 * DINNER)           /* 4096 */
#define XDBLW    (DTRANK + 2 * DSTATE)  /* 96 */

// ---------------- scratch (static device buffers; allocation-free) -------------
__device__ float g_x   [MROWS * DMODEL];
__device__ float g_xz  [MROWS * XZW];
__device__ float g_xa  [MROWS * DINNER];
__device__ float g_xdbl[MROWS * XDBLW];
__device__ float g_dt  [MROWS * DINNER];
__device__ float g_y   [MROWS * DINNER];

// ---------------- helpers ------------------------------------------------------
__device__ __forceinline__ float silu_f(float v) {
    return v / (1.0f + __expf(-v));
}
__device__ __forceinline__ float softplus_f(float v) {
    return fmaxf(v, 0.0f) + log1pf(expf(-fabsf(v)));
}
// packed f32x2 helpers (ptxas never emits FFMA2 on its own — PTX only)
__device__ __forceinline__ unsigned long long splat_f32x2(float a) {
    unsigned long long r;
    unsigned int u = __float_as_uint(a);
    asm("mov.b64 %0, {%1, %1};" : "=l"(r) : "r"(u));
    return r;
}
__device__ __forceinline__ void fma2(unsigned long long& d,
                                     unsigned long long a,
                                     unsigned long long b) {
    asm("fma.rn.f32x2 %0, %1, %2, %0;" : "+l"(d) : "l"(a), "l"(b));
}
__device__ __forceinline__ void unpack_f32x2(unsigned long long v, float& lo, float& hi) {
    unsigned int ulo, uhi;
    asm("mov.b64 {%0, %1}, %2;" : "=r"(ulo), "=r"(uhi) : "l"(v));
    lo = __uint_as_float(ulo);
    hi = __uint_as_float(uhi);
}

// ---------------- 0) x = pe + cond ---------------------------------------------
__global__ void init_x_kernel(const float* __restrict__ pe,
                              const float* __restrict__ condition,
                              const float* __restrict__ cond_w,
                              const float* __restrict__ cond_b,
                              float* __restrict__ x)
{
    int idx = blockIdx.x * blockDim.x + threadIdx.x;
    if (idx >= MROWS * DMODEL) return;
    int d = idx % DMODEL;
    int m = idx / DMODEL;
    int b = m / SEQ;
    int l = m % SEQ;
    x[idx] = pe[l * DMODEL + d] + condition[b] * cond_w[d] + cond_b[d];
}

// ---------------- SGEMM-NT, double-buffered smem + packed f32x2 FFMA -----------
// C[M,N] = A[M,K] * B[N,K]^T.  BK=16.
template<int BM, int BN, int TM, int TN>
__global__ __launch_bounds__(256)
void sgemm_nt(const float* __restrict__ A, const float* __restrict__ B,
              float* __restrict__ C, int M, int N, int K)
{
    constexpr int BK = 16;
    constexpr int THREADS = 256;
    constexpr int TN2 = TN / 2;
    constexpr int RA = (BM * BK + THREADS * 4 - 1) / (THREADS * 4);
    constexpr int RB = (BN * BK + THREADS * 4 - 1) / (THREADS * 4);

    __shared__ __align__(16) float As[2][BK][BM];
    __shared__ __align__(16) float Bs[2][BK][BN];

    const int tid = threadIdx.x;
    const int tx  = tid % (BN / TN);
    const int ty  = tid / (BN / TN);

    const float* Ab = A + (size_t)blockIdx.y * BM * K;
    const float* Bb = B + (size_t)blockIdx.x * BN * K;

    float4 ra[RA], rb[RB];

    auto load_g = [&](int k0) {
#pragma unroll
        for (int it = 0; it < RA; it++) {
            int i = tid * 4 + it * THREADS * 4;
            if (i < BM * BK) {
                int row = i / BK, col = i % BK;
                ra[it] = *(const float4*)(Ab + (size_t)row * K + k0 + col);
            }
        }
#pragma unroll
        for (int it = 0; it < RB; it++) {
            int i = tid * 4 + it * THREADS * 4;
            if (i < BN * BK) {
                int row = i / BK, col = i % BK;
                rb[it] = *(const float4*)(Bb + (size_t)row * K + k0 + col);
            }
        }
    };
    auto store_s = [&](int buf) {
#pragma unroll
        for (int it = 0; it < RA; it++) {
            int i = tid * 4 + it * THREADS * 4;
            if (i < BM * BK) {
                int row = i / BK, col = i % BK;
                As[buf][col + 0][row] = ra[it].x; As[buf][col + 1][row] = ra[it].y;
                As[buf][col + 2][row] = ra[it].z; As[buf][col + 3][row] = ra[it].w;
            }
        }
#pragma unroll
        for (int it = 0; it < RB; it++) {
            int i = tid * 4 + it * THREADS * 4;
            if (i < BN * BK) {
                int row = i / BK, col = i % BK;
                Bs[buf][col + 0][row] = rb[it].x; Bs[buf][col + 1][row] = rb[it].y;
                Bs[buf][col + 2][row] = rb[it].z; Bs[buf][col + 3][row] = rb[it].w;
            }
        }
    };

    unsigned long long acc2[TM][TN2];
#pragma unroll
    for (int i = 0; i < TM; i++)
#pragma unroll
        for (int j = 0; j < TN2; j++) acc2[i][j] = 0ULL;

    auto compute_tile = [&](int buf) {
#pragma unroll
        for (int k = 0; k < BK; k++) {
            unsigned long long b2[TN2];
            const unsigned long long* bsrc =
                (const unsigned long long*)(&Bs[buf][k][tx * TN]);
#pragma unroll
            for (int j = 0; j < TN2; j++) b2[j] = bsrc[j];
#pragma unroll
            for (int i = 0; i < TM; i++) {
                unsigned long long a2 = splat_f32x2(As[buf][k][ty * TM + i]);
#pragma unroll
                for (int j = 0; j < TN2; j++)
                    fma2(acc2[i][j], a2, b2[j]);
            }
        }
    };

    load_g(0);
    store_s(0);
    __syncthreads();

    int cur = 0;
    for (int k0 = BK; k0 < K; k0 += BK) {
        load_g(k0);
        compute_tile(cur);
        store_s(cur ^ 1);
        __syncthreads();
        cur ^= 1;
    }
    compute_tile(cur);

#pragma unroll
    for (int i = 0; i < TM; i++) {
        int row = blockIdx.y * BM + ty * TM + i;
        float* Cr = C + (size_t)row * N + blockIdx.x * BN + tx * TN;
#pragma unroll
        for (int j = 0; j < TN2; j += 2) {
            float4 v;
            unpack_f32x2(acc2[i][j],     v.x, v.y);
            unpack_f32x2(acc2[i][j + 1], v.z, v.w);
            *(float4*)(Cr + 2 * j) = v;
        }
    }
}

// ---------------- 2+3+4) fused conv+SiLU -> x_proj -> dt_proj ------------------
// 8 rows per block, 256 threads, dynamic smem.
__global__ __launch_bounds__(256)
void conv_xproj_dt_kernel(const float* __restrict__ xz,
                          const float* __restrict__ cw,
                          const float* __restrict__ cb,
                          const float* __restrict__ W,
                          const float* __restrict__ dtw,
                          const float* __restrict__ dtb,
                          float* __restrict__ xa,
                          float* __restrict__ xdbl,
                          float* __restrict__ dt)
{
    extern __shared__ float sm[];
    float* rows = sm;                        // [8][DINNER]   64 KB
    float* part = sm + 8 * DINNER;           // [XDBLW][8]     3 KB
    float* dtlr = part + XDBLW * 8;          // [8][DTRANK]    2 KB
    constexpr int D4 = DINNER / 4;
    constexpr int RT = 8;                    // rows per block
    int m0 = blockIdx.x * RT;
    int tid = threadIdx.x;

    // Phase 1: conv + SiLU for 8 rows
    for (int i = tid; i < RT * D4; i += 256) {
        int r  = i / D4;
        int d4 = i % D4;
        int m  = m0 + r;
        int d  = d4 * 4;
        int l  = m % SEQ;
        int base = m - l;                    // b*SEQ

        float4 w0 = *(const float4*)(cw + (size_t)d * 4);
        float4 w1 = *(const float4*)(cw + (size_t)d * 4 + 4);
        float4 w2 = *(const float4*)(cw + (size_t)d * 4 + 8);
        float4 w3 = *(const float4*)(cw + (size_t)d * 4 + 12);
        float4 s  = *(const float4*)(cb + d);

        if (l >= 3) {
            float4 v = *(const float4*)(xz + (size_t)(base + l - 3) * XZW + d);
            s.x += v.x * w0.x; s.y += v.y * w1.x; s.z += v.z * w2.x; s.w += v.w * w3.x;
        }
        if (l >= 2) {
            float4 v = *(const float4*)(xz + (size_t)(base + l - 2) * XZW + d);
            s.x += v.x * w0.y; s.y += v.y * w1.y; s.z += v.z * w2.y; s.w += v.w * w3.y;
        }
        if (l >= 1) {
            float4 v = *(const float4*)(xz + (size_t)(base + l - 1) * XZW + d);
            s.x += v.x * w0.z; s.y += v.y * w1.z; s.z += v.z * w2.z; s.w += v.w * w3.z;
        }
        {
            float4 v = *(const float4*)(xz + (size_t)(base + l) * XZW + d);
            s.x += v.x * w0.w; s.y += v.y * w1.w; s.z += v.z * w2.w; s.w += v.w * w3.w;
        }
        float4 o;
        o.x = silu_f(s.x); o.y = silu_f(s.y); o.z = silu_f(s.z); o.w = silu_f(s.w);
        *(float4*)(&rows[r * DINNER + d]) = o;
        *(float4*)(xa + (size_t)m * DINNER + d) = o;
    }
    __syncthreads();

    // Phase 2: x_proj with K split across two 128-thread groups
    int wg = tid >> 7;               // 0 or 1 (K half)
    int e  = tid & 127;              // output column
    float acc[RT];
#pragma unroll
    for (int r = 0; r < RT; r++) acc[r] = 0.0f;

    if (e < XDBLW) {
        int kbeg = wg * (DINNER / 2);
        const float* wr = W + (size_t)e * DINNER + kbeg;
        const float* rp = rows + kbeg;
        for (int k = 0; k < DINNER / 2; k += 4) {
            float4 w4 = *(const float4*)(wr + k);
#pragma unroll
            for (int r = 0; r < RT; r++) {
                const float* rr = rp + r * DINNER + k;
                acc[r] += rr[0] * w4.x + rr[1] * w4.y + rr[2] * w4.z + rr[3] * w4.w;
            }
        }
    }
    if (wg == 1 && e < XDBLW) {
#pragma unroll
        for (int r = 0; r < RT; r++) part[e * RT + r] = acc[r];
    }
    __syncthreads();
    if (wg == 0 && e < XDBLW) {
#pragma unroll
        for (int r = 0; r < RT; r++) {
            float v = acc[r] + part[e * RT + r];
            xdbl[(size_t)(m0 + r) * XDBLW + e] = v;
            if (e < DTRANK) dtlr[r * DTRANK + e] = v;   // dt_lr slice to smem
        }
    }
    __syncthreads();

    // Phase 3: dt_proj + softplus. Each thread: 8 channels, K=64 from smem.
    for (int c = tid; c < DINNER; c += 256) {
        const float* wr = dtw + (size_t)c * DTRANK;
        float bv = dtb[c];
        float s[RT];
#pragma unroll
        for (int r = 0; r < RT; r++) s[r] = bv;
        for (int k = 0; k < DTRANK; k += 4) {
            float4 w4 = *(const float4*)(wr + k);
#pragma unroll
            for (int r = 0; r < RT; r++) {
                const float* dl = dtlr + r * DTRANK + k;
                s[r] += dl[0] * w4.x + dl[1] * w4.y + dl[2] * w4.z + dl[3] * w4.w;
            }
        }
#pragma unroll
        for (int r = 0; r < RT; r++)
            dt[(size_t)(m0 + r) * DINNER + c] = softplus_f(s[r]);
    }
}

// ---------------- 5) selective scan, 4 lanes/channel, group-of-4 prefetch ------
// 1 warp/SMSP (128 blocks x 128 thr) -> no warp interleave; hide the ~250cyc
// L2 latency with a double-buffered register ring over groups of G=4 steps.
// All per-step operands (dt, xa, z scalars; B/C float4 slices) are fetched one
// full group ahead with ~20 independent loads (MLP>=20), then 4 steps compute.
__global__ __launch_bounds__(128)
void scan_kernel(const float* __restrict__ xdbl, const float* __restrict__ dt,
                 const float* __restrict__ xa, const float* __restrict__ xz,
                 const float* __restrict__ A_log, const float* __restrict__ Dp,
                 float* __restrict__ y)
{
    int t = blockIdx.x * blockDim.x + threadIdx.x;   // 0 .. 4*DINNER-1
    int quad = t & 3;                                // which 4-state group
    int d = t >> 2;
    int b = blockIdx.y;
    if (d >= DINNER) return;

    constexpr int NS = DSTATE / 4;                   // 4 states per lane
    constexpr int G  = 4;                            // timesteps per group
    float a[NS], h[NS];
#pragma unroll
    for (int n = 0; n < NS; n++) {
        a[n] = -expf(A_log[(size_t)d * DSTATE + quad * NS + n]);
        h[n] = 0.0f;
    }
    float Dd = Dp[d];

    const size_t mrow0 = (size_t)b * SEQ;
    const size_t bcoff = DTRANK + quad * NS;         // B slice offset in xdbl row

    float  cdt[G], cxa[G], cz[G];
    float4 cB[G], cC[G];
    float  ndt[G], nxa[G], nz[G];
    float4 nB[G], nC[G];

    // prologue: load group 0
#pragma unroll
    for (int j = 0; j < G; j++) {
        size_t m = mrow0 + j;
        cdt[j] = dt[m * DINNER + d];
        cxa[j] = xa[m * DINNER + d];
        cz[j]  = xz[m * XZW + DINNER + d];
        cB[j]  = *(const float4*)(xdbl + m * XDBLW + bcoff);
        cC[j]  = *(const float4*)(xdbl + m * XDBLW + bcoff + DSTATE);
    }

    for (int l0 = 0; l0 < SEQ; l0 += G) {
        // prefetch group l0+G (independent of the recurrence)
        if (l0 + G < SEQ) {
#pragma unroll
            for (int j = 0; j < G; j++) {
                size_t m = mrow0 + l0 + G + j;
                ndt[j] = dt[m * DINNER + d];
                nxa[j] = xa[m * DINNER + d];
                nz[j]  = xz[m * XZW + DINNER + d];
                nB[j]  = *(const float4*)(xdbl + m * XDBLW + bcoff);
                nC[j]  = *(const float4*)(xdbl + m * XDBLW + bcoff + DSTATE);
            }
        }
        // compute group l0 (overlaps the prefetch latency)
#pragma unroll
        for (int j = 0; j < G; j++) {
            float dtv = cdt[j];
            float xav = cxa[j];
            float dbx = dtv * xav;
            float yv  = (quad == 0) ? xav * Dd : 0.0f;
            float dA0 = __expf(dtv * a[0]);
            float dA1 = __expf(dtv * a[1]);
            float dA2 = __expf(dtv * a[2]);
            float dA3 = __expf(dtv * a[3]);
            h[0] = h[0] * dA0 + dbx * cB[j].x;  yv += h[0] * cC[j].x;
            h[1] = h[1] * dA1 + dbx * cB[j].y;  yv += h[1] * cC[j].y;
            h[2] = h[2] * dA2 + dbx * cB[j].z;  yv += h[2] * cC[j].z;
            h[3] = h[3] * dA3 + dbx * cB[j].w;  yv += h[3] * cC[j].w;
            yv += __shfl_xor_sync(0xffffffffu, yv, 1);
            yv += __shfl_xor_sync(0xffffffffu, yv, 2);
            if (quad == 0)
                y[(mrow0 + l0 + j) * DINNER + d] = yv * silu_f(cz[j]);
        }
        // rotate buffers
#pragma unroll
        for (int j = 0; j < G; j++) {
            cdt[j] = ndt[j]; cxa[j] = nxa[j]; cz[j] = nz[j];
            cB[j] = nB[j];   cC[j] = nC[j];
        }
    }
}

// ---------------- host ----------------------------------------------------------
extern "C" void kernel_launch(void* const* d_in, const int* in_sizes, int n_in,
                              void* d_out, int out_size)
{
    const float* condition = (const float*)d_in[0];
    const float* pe        = (const float*)d_in[1];
    const float* to_cond_w = (const float*)d_in[2];
    const float* to_cond_b = (const float*)d_in[3];
    const float* in_proj_w = (const float*)d_in[4];
    const float* conv_w    = (const float*)d_in[5];
    const float* conv_b    = (const float*)d_in[6];
    const float* x_proj_w  = (const float*)d_in[7];
    const float* dt_proj_w = (const float*)d_in[8];
    const float* dt_proj_b = (const float*)d_in[9];
    const float* A_log     = (const float*)d_in[10];
    const float* D_skip    = (const float*)d_in[11];
    const float* out_proj_w= (const float*)d_in[12];
    // d_in[13] = batch (compile-time constant 2)

    float *x, *xz, *xa, *xdbl, *dt, *y;
    cudaGetSymbolAddress((void**)&x,    g_x);
    cudaGetSymbolAddress((void**)&xz,   g_xz);
    cudaGetSymbolAddress((void**)&xa,   g_xa);
    cudaGetSymbolAddress((void**)&xdbl, g_xdbl);
    cudaGetSymbolAddress((void**)&dt,   g_dt);
    cudaGetSymbolAddress((void**)&y,    g_y);

    // dynamic smem: 8 rows + reduction partials + dt_lr tile (~69 KB)
    const int cx_smem = (8 * DINNER + XDBLW * 8 + 8 * DTRANK) * (int)sizeof(float);
    cudaFuncSetAttribute(conv_xproj_dt_kernel,
                         cudaFuncAttributeMaxDynamicSharedMemorySize, cx_smem);

    init_x_kernel<<<(MROWS * DMODEL + 255) / 256, 256>>>(pe, condition, to_cond_w, to_cond_b, x);

    for (int L = 0; L < NLAYERS; L++) {
        const float* in_w  = in_proj_w  + (size_t)L * XZW * DMODEL;
        const float* cw    = conv_w     + (size_t)L * DINNER * 4;
        const float* cb    = conv_b     + (size_t)L * DINNER;
        const float* xpw   = x_proj_w   + (size_t)L * XDBLW * DINNER;
        const float* dtw   = dt_proj_w  + (size_t)L * DINNER * DTRANK;
        const float* dtb   = dt_proj_b  + (size_t)L * DINNER;
        const float* Al    = A_log      + (size_t)L * DINNER * DSTATE;
        const float* Dpl   = D_skip     + (size_t)L * DINNER;
        const float* ow    = out_proj_w + (size_t)L * DMODEL * DINNER;

        // xz = x * in_w^T   (M=1024, N=4096, K=1024)
        sgemm_nt<128, 128, 8, 8><<<dim3(XZW / 128, MROWS / 128), 256>>>(
            x, in_w, xz, MROWS, XZW, DMODEL);

        // fused conv+SiLU -> xa, x_proj -> xdbl, dt_proj+softplus -> dt
        conv_xproj_dt_kernel<<<MROWS / 8, 256, cx_smem>>>(
            xz, cw, cb, xpw, dtw, dtb, xa, xdbl, dt);

        // 4 lanes per channel: 4*DINNER threads per batch
        scan_kernel<<<dim3(4 * DINNER / 128, BATCH), 128>>>(xdbl, dt, xa, xz, Al, Dpl, y);

        float* Cout = (L == NLAYERS - 1) ? (float*)d_out : x;
        // out = y * out_w^T  (M=1024, N=1024, K=2048)
        sgemm_nt<64, 128, 4, 8><<<dim3(DMODEL / 128, MROWS / 64), 256>>>(
            y, ow, Cout, MROWS, DMODEL, DINNER);
    }
}

// round 14
// speedup vs baseline: 1.5154x; 1.5154x over previous
#include <cuda_runtime.h>
#include <cuda_bf16.h>
#include <math.h>
#include <stdint.h>

#define SEQ      512
#define BATCH    2
#define DMODEL   1024
#define DINNER   2048
#define DSTATE   16
#define DTRANK   64
#define NLAYERS  4
#define MROWS    (BATCH * SEQ)          /* 1024 */
#define XZW      (2 * DINNER)           /* 4096 */
#define XDBLW    (DTRANK + 2 * DSTATE)  /* 96 */

// ---------------- scratch (static device buffers; allocation-free) -------------
__device__ float g_x   [MROWS * DMODEL];
__device__ float g_xz  [MROWS * XZW];
__device__ float g_xa  [MROWS * DINNER];
__device__ float g_xdbl[MROWS * XDBLW];
__device__ float g_dt  [MROWS * DINNER];
__device__ float g_y   [MROWS * DINNER];

// ---------------- helpers ------------------------------------------------------
__device__ __forceinline__ float silu_f(float v) {
    return v / (1.0f + __expf(-v));
}
__device__ __forceinline__ float softplus_f(float v) {
    return fmaxf(v, 0.0f) + log1pf(expf(-fabsf(v)));
}

// ---------------- 0) x = pe + cond ---------------------------------------------
__global__ void init_x_kernel(const float* __restrict__ pe,
                              const float* __restrict__ condition,
                              const float* __restrict__ cond_w,
                              const float* __restrict__ cond_b,
                              float* __restrict__ x)
{
    int idx = blockIdx.x * blockDim.x + threadIdx.x;
    if (idx >= MROWS * DMODEL) return;
    int d = idx % DMODEL;
    int m = idx / DMODEL;
    int b = m / SEQ;
    int l = m % SEQ;
    x[idx] = pe[l * DMODEL + d] + condition[b] * cond_w[d] + cond_b[d];
}

// ---------------- bf16 3-term split GEMM-NT via mma.sync ------------------------
// C[M,N] = A[M,K] * B[N,K]^T, fp32 in/out.
// Each fp32 operand splits to bf16 hi + bf16 lo; D += Ahi*Bhi + Ahi*Blo + Alo*Bhi
// (fp32 accumulate). Dropped lo*lo term is ~2^-32 relative per product.
// m16n8k16 fragment layouts per PTX ISA (A row-major, B col-major == our NT).
__device__ __forceinline__ void mma16816(float* c, const uint32_t* a, const uint32_t* b)
{
    asm volatile(
        "mma.sync.aligned.m16n8k16.row.col.f32.bf16.bf16.f32 "
        "{%0,%1,%2,%3}, {%4,%5,%6,%7}, {%8,%9}, {%0,%1,%2,%3};"
        : "+f"(c[0]), "+f"(c[1]), "+f"(c[2]), "+f"(c[3])
        : "r"(a[0]), "r"(a[1]), "r"(a[2]), "r"(a[3]), "r"(b[0]), "r"(b[1]));
}

template<int BM, int BN>
__global__ __launch_bounds__(256)
void mma_gemm_nt(const float* __restrict__ A, const float* __restrict__ B,
                 float* __restrict__ C, int M, int N, int K)
{
    constexpr int BK = 16;
    constexpr int MT = (BM / 2) / 16;    // mma M-tiles per warp (warps: 2 x 4)
    constexpr int NT = (BN / 4) / 8;     // mma N-tiles per warp
    constexpr int LA = BM * BK / 4 / 256;  // float4 loads per thread (A)
    constexpr int LB = BN * BK / 4 / 256;  // float4 loads per thread (B)

    __shared__ __align__(16) __nv_bfloat16 As[2][2][BM][BK];  // [buf][hi/lo]
    __shared__ __align__(16) __nv_bfloat16 Bs[2][2][BN][BK];

    const int tid  = threadIdx.x;
    const int lane = tid & 31;
    const int wid  = tid >> 5;
    const int wm   = wid >> 2;           // 0..1
    const int wn   = wid & 3;            // 0..3
    const int g    = lane >> 2;          // 0..7 (row group)
    const int qp   = (lane & 3) * 2;     // k/col pair base

    const float* Ab = A + (size_t)blockIdx.y * BM * K;
    const float* Bb = B + (size_t)blockIdx.x * BN * K;

    float4 ra[LA], rb[LB];

    auto load_g = [&](int k0) {
#pragma unroll
        for (int it = 0; it < LA; it++) {
            int i = tid + it * 256;
            int row = i >> 2, kc = (i & 3) * 4;
            ra[it] = *(const float4*)(Ab + (size_t)row * K + k0 + kc);
        }
#pragma unroll
        for (int it = 0; it < LB; it++) {
            int i = tid + it * 256;
            int row = i >> 2, kc = (i & 3) * 4;
            rb[it] = *(const float4*)(Bb + (size_t)row * K + k0 + kc);
        }
    };

    auto store_s = [&](int buf) {
#pragma unroll
        for (int it = 0; it < LA; it++) {
            int i = tid + it * 256;
            int row = i >> 2, kc = (i & 3) * 4;
            float4 v = ra[it];
            __nv_bfloat16 h0 = __float2bfloat16(v.x);
            __nv_bfloat16 h1 = __float2bfloat16(v.y);
            __nv_bfloat16 h2 = __float2bfloat16(v.z);
            __nv_bfloat16 h3 = __float2bfloat16(v.w);
            *(__nv_bfloat162*)&As[buf][0][row][kc]     = __halves2bfloat162(h0, h1);
            *(__nv_bfloat162*)&As[buf][0][row][kc + 2] = __halves2bfloat162(h2, h3);
            __nv_bfloat16 l0 = __float2bfloat16(v.x - __bfloat162float(h0));
            __nv_bfloat16 l1 = __float2bfloat16(v.y - __bfloat162float(h1));
            __nv_bfloat16 l2 = __float2bfloat16(v.z - __bfloat162float(h2));
            __nv_bfloat16 l3 = __float2bfloat16(v.w - __bfloat162float(h3));
            *(__nv_bfloat162*)&As[buf][1][row][kc]     = __halves2bfloat162(l0, l1);
            *(__nv_bfloat162*)&As[buf][1][row][kc + 2] = __halves2bfloat162(l2, l3);
        }
#pragma unroll
        for (int it = 0; it < LB; it++) {
            int i = tid + it * 256;
            int row = i >> 2, kc = (i & 3) * 4;
            float4 v = rb[it];
            __nv_bfloat16 h0 = __float2bfloat16(v.x);
            __nv_bfloat16 h1 = __float2bfloat16(v.y);
            __nv_bfloat16 h2 = __float2bfloat16(v.z);
            __nv_bfloat16 h3 = __float2bfloat16(v.w);
            *(__nv_bfloat162*)&Bs[buf][0][row][kc]     = __halves2bfloat162(h0, h1);
            *(__nv_bfloat162*)&Bs[buf][0][row][kc + 2] = __halves2bfloat162(h2, h3);
            __nv_bfloat16 l0 = __float2bfloat16(v.x - __bfloat162float(h0));
            __nv_bfloat16 l1 = __float2bfloat16(v.y - __bfloat162float(h1));
            __nv_bfloat16 l2 = __float2bfloat16(v.z - __bfloat162float(h2));
            __nv_bfloat16 l3 = __float2bfloat16(v.w - __bfloat162float(h3));
            *(__nv_bfloat162*)&Bs[buf][1][row][kc]     = __halves2bfloat162(l0, l1);
            *(__nv_bfloat162*)&Bs[buf][1][row][kc + 2] = __halves2bfloat162(l2, l3);
        }
    };

    float acc[MT][NT][4];
#pragma unroll
    for (int mi = 0; mi < MT; mi++)
#pragma unroll
        for (int ni = 0; ni < NT; ni++)
#pragma unroll
            for (int q = 0; q < 4; q++) acc[mi][ni][q] = 0.0f;

    auto compute = [&](int buf) {
        uint32_t afh[MT][4], afl[MT][4], bfh[NT][2], bfl[NT][2];
#pragma unroll
        for (int mi = 0; mi < MT; mi++) {
            int m = wm * (BM / 2) + mi * 16;
            afh[mi][0] = *(const uint32_t*)&As[buf][0][m + g][qp];
            afh[mi][1] = *(const uint32_t*)&As[buf][0][m + g + 8][qp];
            afh[mi][2] = *(const uint32_t*)&As[buf][0][m + g][qp + 8];
            afh[mi][3] = *(const uint32_t*)&As[buf][0][m + g + 8][qp + 8];
            afl[mi][0] = *(const uint32_t*)&As[buf][1][m + g][qp];
            afl[mi][1] = *(const uint32_t*)&As[buf][1][m + g + 8][qp];
            afl[mi][2] = *(const uint32_t*)&As[buf][1][m + g][qp + 8];
            afl[mi][3] = *(const uint32_t*)&As[buf][1][m + g + 8][qp + 8];
        }
#pragma unroll
        for (int ni = 0; ni < NT; ni++) {
            int n = wn * (BN / 4) + ni * 8;
            bfh[ni][0] = *(const uint32_t*)&Bs[buf][0][n + g][qp];
            bfh[ni][1] = *(const uint32_t*)&Bs[buf][0][n + g][qp + 8];
            bfl[ni][0] = *(const uint32_t*)&Bs[buf][1][n + g][qp];
            bfl[ni][1] = *(const uint32_t*)&Bs[buf][1][n + g][qp + 8];
        }
#pragma unroll
        for (int mi = 0; mi < MT; mi++)
#pragma unroll
            for (int ni = 0; ni < NT; ni++) {
                mma16816(acc[mi][ni], afh[mi], bfh[ni]);
                mma16816(acc[mi][ni], afh[mi], bfl[ni]);
                mma16816(acc[mi][ni], afl[mi], bfh[ni]);
            }
    };

    load_g(0);
    store_s(0);
    __syncthreads();

    int cur = 0;
    for (int k0 = BK; k0 < K; k0 += BK) {
        load_g(k0);            // next chunk (overlaps compute)
        compute(cur);
        store_s(cur ^ 1);
        __syncthreads();
        cur ^= 1;
    }
    compute(cur);

    // epilogue: c0,c1 -> (row, col..col+1); c2,c3 -> (row+8, ...)
#pragma unroll
    for (int mi = 0; mi < MT; mi++) {
#pragma unroll
        for (int ni = 0; ni < NT; ni++) {
            int row = blockIdx.y * BM + wm * (BM / 2) + mi * 16 + g;
            int col = blockIdx.x * BN + wn * (BN / 4) + ni * 8 + qp;
            float2 v0 = make_float2(acc[mi][ni][0], acc[mi][ni][1]);
            float2 v1 = make_float2(acc[mi][ni][2], acc[mi][ni][3]);
            *(float2*)&C[(size_t)row * N + col]       = v0;
            *(float2*)&C[(size_t)(row + 8) * N + col] = v1;
        }
    }
}

// ---------------- 2+3+4) fused conv+SiLU -> x_proj -> dt_proj ------------------
__global__ __launch_bounds__(256)
void conv_xproj_dt_kernel(const float* __restrict__ xz,
                          const float* __restrict__ cw,
                          const float* __restrict__ cb,
                          const float* __restrict__ W,
                          const float* __restrict__ dtw,
                          const float* __restrict__ dtb,
                          float* __restrict__ xa,
                          float* __restrict__ xdbl,
                          float* __restrict__ dt)
{
    extern __shared__ float sm[];
    float* rows = sm;                        // [8][DINNER]   64 KB
    float* part = sm + 8 * DINNER;           // [XDBLW][8]     3 KB
    float* dtlr = part + XDBLW * 8;          // [8][DTRANK]    2 KB
    constexpr int D4 = DINNER / 4;
    constexpr int RT = 8;                    // rows per block
    int m0 = blockIdx.x * RT;
    int tid = threadIdx.x;

    // Phase 1: conv + SiLU for 8 rows
    for (int i = tid; i < RT * D4; i += 256) {
        int r  = i / D4;
        int d4 = i % D4;
        int m  = m0 + r;
        int d  = d4 * 4;
        int l  = m % SEQ;
        int base = m - l;                    // b*SEQ

        float4 w0 = *(const float4*)(cw + (size_t)d * 4);
        float4 w1 = *(const float4*)(cw + (size_t)d * 4 + 4);
        float4 w2 = *(const float4*)(cw + (size_t)d * 4 + 8);
        float4 w3 = *(const float4*)(cw + (size_t)d * 4 + 12);
        float4 s  = *(const float4*)(cb + d);

        if (l >= 3) {
            float4 v = *(const float4*)(xz + (size_t)(base + l - 3) * XZW + d);
            s.x += v.x * w0.x; s.y += v.y * w1.x; s.z += v.z * w2.x; s.w += v.w * w3.x;
        }
        if (l >= 2) {
            float4 v = *(const float4*)(xz + (size_t)(base + l - 2) * XZW + d);
            s.x += v.x * w0.y; s.y += v.y * w1.y; s.z += v.z * w2.y; s.w += v.w * w3.y;
        }
        if (l >= 1) {
            float4 v = *(const float4*)(xz + (size_t)(base + l - 1) * XZW + d);
            s.x += v.x * w0.z; s.y += v.y * w1.z; s.z += v.z * w2.z; s.w += v.w * w3.z;
        }
        {
            float4 v = *(const float4*)(xz + (size_t)(base + l) * XZW + d);
            s.x += v.x * w0.w; s.y += v.y * w1.w; s.z += v.z * w2.w; s.w += v.w * w3.w;
        }
        float4 o;
        o.x = silu_f(s.x); o.y = silu_f(s.y); o.z = silu_f(s.z); o.w = silu_f(s.w);
        *(float4*)(&rows[r * DINNER + d]) = o;
        *(float4*)(xa + (size_t)m * DINNER + d) = o;
    }
    __syncthreads();

    // Phase 2: x_proj with K split across two 128-thread groups
    int wg = tid >> 7;               // 0 or 1 (K half)
    int e  = tid & 127;              // output column
    float acc[RT];
#pragma unroll
    for (int r = 0; r < RT; r++) acc[r] = 0.0f;

    if (e < XDBLW) {
        int kbeg = wg * (DINNER / 2);
        const float* wr = W + (size_t)e * DINNER + kbeg;
        const float* rp = rows + kbeg;
        for (int k = 0; k < DINNER / 2; k += 4) {
            float4 w4 = *(const float4*)(wr + k);
#pragma unroll
            for (int r = 0; r < RT; r++) {
                const float* rr = rp + r * DINNER + k;
                acc[r] += rr[0] * w4.x + rr[1] * w4.y + rr[2] * w4.z + rr[3] * w4.w;
            }
        }
    }
    if (wg == 1 && e < XDBLW) {
#pragma unroll
        for (int r = 0; r < RT; r++) part[e * RT + r] = acc[r];
    }
    __syncthreads();
    if (wg == 0 && e < XDBLW) {
#pragma unroll
        for (int r = 0; r < RT; r++) {
            float v = acc[r] + part[e * RT + r];
            xdbl[(size_t)(m0 + r) * XDBLW + e] = v;
            if (e < DTRANK) dtlr[r * DTRANK + e] = v;   // dt_lr slice to smem
        }
    }
    __syncthreads();

    // Phase 3: dt_proj + softplus
    for (int c = tid; c < DINNER; c += 256) {
        const float* wr = dtw + (size_t)c * DTRANK;
        float bv = dtb[c];
        float s[RT];
#pragma unroll
        for (int r = 0; r < RT; r++) s[r] = bv;
        for (int k = 0; k < DTRANK; k += 4) {
            float4 w4 = *(const float4*)(wr + k);
#pragma unroll
            for (int r = 0; r < RT; r++) {
                const float* dl = dtlr + r * DTRANK + k;
                s[r] += dl[0] * w4.x + dl[1] * w4.y + dl[2] * w4.z + dl[3] * w4.w;
            }
        }
#pragma unroll
        for (int r = 0; r < RT; r++)
            dt[(size_t)(m0 + r) * DINNER + c] = softplus_f(s[r]);
    }
}

// ---------------- 5) selective scan, 4 lanes/channel, group-of-4 prefetch ------
__global__ __launch_bounds__(128)
void scan_kernel(const float* __restrict__ xdbl, const float* __restrict__ dt,
                 const float* __restrict__ xa, const float* __restrict__ xz,
                 const float* __restrict__ A_log, const float* __restrict__ Dp,
                 float* __restrict__ y)
{
    int t = blockIdx.x * blockDim.x + threadIdx.x;   // 0 .. 4*DINNER-1
    int quad = t & 3;                                // which 4-state group
    int d = t >> 2;
    int b = blockIdx.y;
    if (d >= DINNER) return;

    constexpr int NS = DSTATE / 4;                   // 4 states per lane
    constexpr int G  = 4;                            // timesteps per group
    float a[NS], h[NS];
#pragma unroll
    for (int n = 0; n < NS; n++) {
        a[n] = -expf(A_log[(size_t)d * DSTATE + quad * NS + n]);
        h[n] = 0.0f;
    }
    float Dd = Dp[d];

    const size_t mrow0 = (size_t)b * SEQ;
    const size_t bcoff = DTRANK + quad * NS;         // B slice offset in xdbl row

    float  cdt[G], cxa[G], cz[G];
    float4 cB[G], cC[G];
    float  ndt[G], nxa[G], nz[G];
    float4 nB[G], nC[G];

#pragma unroll
    for (int j = 0; j < G; j++) {
        size_t m = mrow0 + j;
        cdt[j] = dt[m * DINNER + d];
        cxa[j] = xa[m * DINNER + d];
        cz[j]  = xz[m * XZW + DINNER + d];
        cB[j]  = *(const float4*)(xdbl + m * XDBLW + bcoff);
        cC[j]  = *(const float4*)(xdbl + m * XDBLW + bcoff + DSTATE);
    }

    for (int l0 = 0; l0 < SEQ; l0 += G) {
        if (l0 + G < SEQ) {
#pragma unroll
            for (int j = 0; j < G; j++) {
                size_t m = mrow0 + l0 + G + j;
                ndt[j] = dt[m * DINNER + d];
                nxa[j] = xa[m * DINNER + d];
                nz[j]  = xz[m * XZW + DINNER + d];
                nB[j]  = *(const float4*)(xdbl + m * XDBLW + bcoff);
                nC[j]  = *(const float4*)(xdbl + m * XDBLW + bcoff + DSTATE);
            }
        }
#pragma unroll
        for (int j = 0; j < G; j++) {
            float dtv = cdt[j];
            float xav = cxa[j];
            float dbx = dtv * xav;
            float yv  = (quad == 0) ? xav * Dd : 0.0f;
            float dA0 = __expf(dtv * a[0]);
            float dA1 = __expf(dtv * a[1]);
            float dA2 = __expf(dtv * a[2]);
            float dA3 = __expf(dtv * a[3]);
            h[0] = h[0] * dA0 + dbx * cB[j].x;  yv += h[0] * cC[j].x;
            h[1] = h[1] * dA1 + dbx * cB[j].y;  yv += h[1] * cC[j].y;
            h[2] = h[2] * dA2 + dbx * cB[j].z;  yv += h[2] * cC[j].z;
            h[3] = h[3] * dA3 + dbx * cB[j].w;  yv += h[3] * cC[j].w;
            yv += __shfl_xor_sync(0xffffffffu, yv, 1);
            yv += __shfl_xor_sync(0xffffffffu, yv, 2);
            if (quad == 0)
                y[(mrow0 + l0 + j) * DINNER + d] = yv * silu_f(cz[j]);
        }
#pragma unroll
        for (int j = 0; j < G; j++) {
            cdt[j] = ndt[j]; cxa[j] = nxa[j]; cz[j] = nz[j];
            cB[j] = nB[j];   cC[j] = nC[j];
        }
    }
}

// ---------------- host ----------------------------------------------------------
extern "C" void kernel_launch(void* const* d_in, const int* in_sizes, int n_in,
                              void* d_out, int out_size)
{
    const float* condition = (const float*)d_in[0];
    const float* pe        = (const float*)d_in[1];
    const float* to_cond_w = (const float*)d_in[2];
    const float* to_cond_b = (const float*)d_in[3];
    const float* in_proj_w = (const float*)d_in[4];
    const float* conv_w    = (const float*)d_in[5];
    const float* conv_b    = (const float*)d_in[6];
    const float* x_proj_w  = (const float*)d_in[7];
    const float* dt_proj_w = (const float*)d_in[8];
    const float* dt_proj_b = (const float*)d_in[9];
    const float* A_log     = (const float*)d_in[10];
    const float* D_skip    = (const float*)d_in[11];
    const float* out_proj_w= (const float*)d_in[12];
    // d_in[13] = batch (compile-time constant 2)

    float *x, *xz, *xa, *xdbl, *dt, *y;
    cudaGetSymbolAddress((void**)&x,    g_x);
    cudaGetSymbolAddress((void**)&xz,   g_xz);
    cudaGetSymbolAddress((void**)&xa,   g_xa);
    cudaGetSymbolAddress((void**)&xdbl, g_xdbl);
    cudaGetSymbolAddress((void**)&dt,   g_dt);
    cudaGetSymbolAddress((void**)&y,    g_y);

    // dynamic smem: 8 rows + reduction partials + dt_lr tile (~69 KB)
    const int cx_smem = (8 * DINNER + XDBLW * 8 + 8 * DTRANK) * (int)sizeof(float);
    cudaFuncSetAttribute(conv_xproj_dt_kernel,
                         cudaFuncAttributeMaxDynamicSharedMemorySize, cx_smem);

    init_x_kernel<<<(MROWS * DMODEL + 255) / 256, 256>>>(pe, condition, to_cond_w, to_cond_b, x);

    for (int L = 0; L < NLAYERS; L++) {
        const float* in_w  = in_proj_w  + (size_t)L * XZW * DMODEL;
        const float* cw    = conv_w     + (size_t)L * DINNER * 4;
        const float* cb    = conv_b     + (size_t)L * DINNER;
        const float* xpw   = x_proj_w   + (size_t)L * XDBLW * DINNER;
        const float* dtw   = dt_proj_w  + (size_t)L * DINNER * DTRANK;
        const float* dtb   = dt_proj_b  + (size_t)L * DINNER;
        const float* Al    = A_log      + (size_t)L * DINNER * DSTATE;
        const float* Dpl   = D_skip     + (size_t)L * DINNER;
        const float* ow    = out_proj_w + (size_t)L * DMODEL * DINNER;

        // xz = x * in_w^T   (M=1024, N=4096, K=1024) — tensor cores, 3x bf16
        mma_gemm_nt<128, 128><<<dim3(XZW / 128, MROWS / 128), 256>>>(
            x, in_w, xz, MROWS, XZW, DMODEL);

        // fused conv+SiLU -> xa, x_proj -> xdbl, dt_proj+softplus -> dt
        conv_xproj_dt_kernel<<<MROWS / 8, 256, cx_smem>>>(
            xz, cw, cb, xpw, dtw, dtb, xa, xdbl, dt);

        // 4 lanes per channel: 4*DINNER threads per batch
        scan_kernel<<<dim3(4 * DINNER / 128, BATCH), 128>>>(xdbl, dt, xa, xz, Al, Dpl, y);

        float* Cout = (L == NLAYERS - 1) ? (float*)d_out : x;
        // out = y * out_w^T  (M=1024, N=1024, K=2048) — tensor cores, 3x bf16
        mma_gemm_nt<64, 128><<<dim3(DMODEL / 128, MROWS / 64), 256>>>(
            y, ow, Cout, MROWS, DMODEL, DINNER);
    }
}